// round 16
// baseline (speedup 1.0000x reference)
#include <cuda_runtime.h>
#include <cuda_fp16.h>
#include <mma.h>
#include <math.h>
#include <float.h>

using namespace nvcuda;

#define MAXN 20000
#define MAXNP 20032
#define MAXE 150000
#define C1 512
#define H1 4
#define C2 128
#define K1P 48
#define NCHUNK 2

// ---------------- scratch ----------------
static __device__ __half g_h0h[MAXNP * K1P];   // fp16 concat(x, aa_emb[rt]), padded to 48
static __device__ __half g_xl1h[MAXNP * C1];   // gather-side features, fp16
static __device__ __half g_xr1h[MAXNP * C1];   // dst-side features, fp16
static __device__ __half g_h1h[MAXNP * C1];    // layer-1 output, fp16 (gemm2 A operand)
static __device__ __half g_xl2h[MAXNP * C2];
static __device__ __half g_xr2h[MAXNP * C2];
static __device__ float  g_easum[MAXN * 2];
static __device__ float  g_loopea[MAXN * 2];
static __device__ int    g_deg[MAXN];
static __device__ int    g_rowstart[MAXN + 1];
static __device__ int    g_cursor[MAXN];
static __device__ int    g_esrc[MAXE];         // src permuted into CSR order
static __device__ float2 g_eea[MAXE];          // edge_attr permuted into CSR order
static __device__ int    g_blocksum[32];

// ---------------- per-node init ----------------
__global__ void k_init(int N) {
    int i = blockIdx.x * blockDim.x + threadIdx.x;
    if (i >= N) return;
    g_deg[i] = 0;
    g_cursor[i] = 0;
    g_easum[2 * i] = 0.f;
    g_easum[2 * i + 1] = 0.f;
}

// ---------------- fp16 h0 = concat(x, aa_emb[rt]) padded to 48; one uint4 per thread ----------------
__global__ void k_h0h(const float* __restrict__ x, const int* __restrict__ rt,
                      const float* __restrict__ aaemb, int N) {
    int idx = blockIdx.x * blockDim.x + threadIdx.x;   // N*6 uint4 groups
    if (idx >= N * 6) return;
    int n = idx / 6, g = idx - n * 6;
    int c0 = g * 8;
    int r = __ldg(rt + n);
    __half h[8];
#pragma unroll
    for (int j = 0; j < 8; j++) {
        int c = c0 + j;
        float v = 0.f;
        if (c < 5) v = __ldg(x + n * 5 + c);
        else if (c < 37) v = __ldg(aaemb + r * 32 + (c - 5));
        h[j] = __float2half(v);
    }
    *(uint4*)(g_h0h + (long)n * K1P + c0) = *(uint4*)h;
}

// ---------------- degree + edge-attr sums ----------------
__global__ void k_deg(const int* __restrict__ dst, const float* __restrict__ ea, int E) {
    int e = blockIdx.x * blockDim.x + threadIdx.x;
    if (e >= E) return;
    int d = dst[e];
    float2 a = ((const float2*)ea)[e];
    atomicAdd(&g_deg[d], 1);
    atomicAdd(&g_easum[2 * d], a.x);
    atomicAdd(&g_easum[2 * d + 1], a.y);
}

// ---------------- parallel scan (2 kernels) ----------------
__global__ void k_scan1(int N) {
    __shared__ int sm[1024];
    int i = blockIdx.x * 1024 + threadIdx.x;
    int v = (i < N) ? g_deg[i] : 0;
    sm[threadIdx.x] = v;
    __syncthreads();
    for (int o = 1; o < 1024; o <<= 1) {
        int t = (threadIdx.x >= o) ? sm[threadIdx.x - o] : 0;
        __syncthreads();
        sm[threadIdx.x] += t;
        __syncthreads();
    }
    if (i < N) g_rowstart[i] = sm[threadIdx.x] - v;
    if (threadIdx.x == 1023) g_blocksum[blockIdx.x] = sm[1023];
}
__global__ void k_scan3(int N, int nb) {
    __shared__ int soff[32];
    int t = threadIdx.x;
    if (t < 32) {
        int v = (t < nb) ? g_blocksum[t] : 0;
        int s = v;
#pragma unroll
        for (int o = 1; o < 32; o <<= 1) {
            int u = __shfl_up_sync(0xffffffffu, s, o);
            if (t >= o) s += u;
        }
        soff[t] = s - v;
    }
    __syncthreads();
    int i = blockIdx.x * blockDim.x + t;
    if (i < N) {
        g_rowstart[i] += soff[i >> 10];
        int dg = g_deg[i];
        float fd = (dg < 1) ? 1.f : (float)dg;
        g_loopea[2 * i]     = g_easum[2 * i] / fd;
        g_loopea[2 * i + 1] = g_easum[2 * i + 1] / fd;
    }
    if (i == 0) g_rowstart[N] = soff[31];
}

__global__ void k_scatter(const int* __restrict__ src, const int* __restrict__ dst,
                          const float* __restrict__ ea, int E) {
    int e = blockIdx.x * blockDim.x + threadIdx.x;
    if (e >= E) return;
    int d = dst[e];
    int pos = g_rowstart[d] + atomicAdd(&g_cursor[d], 1);
    g_esrc[pos] = src[e];
    g_eea[pos] = ((const float2*)ea)[e];
}

// ---- epilogue helper: warp writes one 16x16 fp32 tile (ldm=16) as fp16 (16B stores) ----
__device__ __forceinline__ void tile_to_half(const float* st, __half* gbase,
                                             long grow0, int gcol0, int ldg_, int lane) {
    int row = lane >> 1, colh = (lane & 1) * 8;
    const float* sp = st + row * 16 + colh;
    __half2 h0 = __floats2half2_rn(sp[0], sp[1]);
    __half2 h1 = __floats2half2_rn(sp[2], sp[3]);
    __half2 h2 = __floats2half2_rn(sp[4], sp[5]);
    __half2 h3 = __floats2half2_rn(sp[6], sp[7]);
    uint4 u = make_uint4(*(unsigned*)&h0, *(unsigned*)&h1, *(unsigned*)&h2, *(unsigned*)&h3);
    *(uint4*)(gbase + (grow0 + row) * ldg_ + gcol0 + colh) = u;
}

// ---------------- layer-1 GEMM (fp16 WMMA m16n16k16): h0h[NP,48] @ [48,512] ----------------
__global__ void __launch_bounds__(256) k_gemm1(const float* __restrict__ Wl,
                                               const float* __restrict__ Wr, int N) {
    const float* W = blockIdx.z ? Wr : Wl;
    __half* outh = blockIdx.z ? g_xr1h : g_xl1h;
    __shared__ __half Ah[64 * 56];
    __shared__ __half Bh[K1P * 136];
    __shared__ float stg[8 * 256];
    int tid = threadIdx.x;
    int n0 = blockIdx.x * 64;
    int col0 = blockIdx.y * 128;
    // A: 64 rows x 48 halves = 384 uint4, pure copy from precomputed h0h
    for (int idx = tid; idx < 64 * 6; idx += 256) {
        int r = idx / 6, g = idx - r * 6;
        uint4 u = make_uint4(0, 0, 0, 0);
        if (n0 + r < N) u = *(const uint4*)(g_h0h + (long)(n0 + r) * K1P + g * 8);
        *(uint4*)(Ah + r * 56 + g * 8) = u;
    }
    for (int idx = tid; idx < K1P * 128; idx += 256) {
        int r = idx >> 7, c = idx & 127;
        float v = (r < 37) ? W[r * C1 + col0 + c] : 0.f;
        Bh[r * 136 + c] = __float2half(v);
    }
    __syncthreads();
    int wid = tid >> 5, lane = tid & 31;
    int wr = wid & 1, wc = wid >> 1;
    wmma::fragment<wmma::accumulator, 16, 16, 16, float> acc[2][2];
#pragma unroll
    for (int i = 0; i < 2; i++)
#pragma unroll
        for (int j = 0; j < 2; j++) wmma::fill_fragment(acc[i][j], 0.f);
#pragma unroll
    for (int kk = 0; kk < K1P; kk += 16) {
        wmma::fragment<wmma::matrix_a, 16, 16, 16, __half, wmma::row_major> a[2];
        wmma::fragment<wmma::matrix_b, 16, 16, 16, __half, wmma::row_major> b[2];
#pragma unroll
        for (int i = 0; i < 2; i++)
            wmma::load_matrix_sync(a[i], &Ah[(wr * 32 + i * 16) * 56 + kk], 56);
#pragma unroll
        for (int j = 0; j < 2; j++)
            wmma::load_matrix_sync(b[j], &Bh[kk * 136 + wc * 32 + j * 16], 136);
#pragma unroll
        for (int i = 0; i < 2; i++)
#pragma unroll
            for (int j = 0; j < 2; j++)
                wmma::mma_sync(acc[i][j], a[i], b[j], acc[i][j]);
    }
    float* st = stg + wid * 256;
#pragma unroll
    for (int i = 0; i < 2; i++)
#pragma unroll
        for (int j = 0; j < 2; j++) {
            wmma::store_matrix_sync(st, acc[i][j], 16, wmma::mem_row_major);
            __syncwarp();
            tile_to_half(st, outh, n0 + wr * 32 + i * 16,
                         col0 + wc * 32 + j * 16, C1, lane);
            __syncwarp();
        }
}

// ---------------- layer-2 GEMM (fp16 WMMA m16n16k16) over node chunk [ns, ...) ----------------
__global__ void __launch_bounds__(256) k_gemm2(const float* __restrict__ Wl,
                                               const float* __restrict__ Wr,
                                               int ns, int N) {
    const float* W = blockIdx.z ? Wr : Wl;
    __half* outh = blockIdx.z ? g_xr2h : g_xl2h;
    __shared__ __half Ah[64 * 40];
    __shared__ __half Bh[32 * 136];
    __shared__ float stg[8 * 256];
    int tid = threadIdx.x;
    int n0 = ns + blockIdx.x * 64;
    int wid = tid >> 5, lane = tid & 31;
    int wr = wid & 1, wc = wid >> 1;
    wmma::fragment<wmma::accumulator, 16, 16, 16, float> acc[2][2];
#pragma unroll
    for (int i = 0; i < 2; i++)
#pragma unroll
        for (int j = 0; j < 2; j++) wmma::fill_fragment(acc[i][j], 0.f);
    for (int k0 = 0; k0 < C1; k0 += 32) {
        {   // A: 64x32 halves, one uint4 (8 halves) per thread
            int r = tid >> 2, g = (tid & 3) * 8;
            uint4 u = make_uint4(0, 0, 0, 0);
            if (n0 + r < N)
                u = *(const uint4*)(g_h1h + (long)(n0 + r) * C1 + k0 + g);
            *(uint4*)(Ah + r * 40 + g) = u;
        }
        for (int idx = tid; idx < 32 * 128; idx += 256) {
            int r = idx >> 7, c = idx & 127;
            Bh[r * 136 + c] = __float2half(W[(k0 + r) * C2 + c]);
        }
        __syncthreads();
#pragma unroll
        for (int kk = 0; kk < 32; kk += 16) {
            wmma::fragment<wmma::matrix_a, 16, 16, 16, __half, wmma::row_major> a[2];
            wmma::fragment<wmma::matrix_b, 16, 16, 16, __half, wmma::row_major> b[2];
#pragma unroll
            for (int i = 0; i < 2; i++)
                wmma::load_matrix_sync(a[i], &Ah[(wr * 32 + i * 16) * 40 + kk], 40);
#pragma unroll
            for (int j = 0; j < 2; j++)
                wmma::load_matrix_sync(b[j], &Bh[kk * 136 + wc * 32 + j * 16], 136);
#pragma unroll
            for (int i = 0; i < 2; i++)
#pragma unroll
                for (int j = 0; j < 2; j++)
                    wmma::mma_sync(acc[i][j], a[i], b[j], acc[i][j]);
        }
        __syncthreads();
    }
    float* st = stg + wid * 256;
#pragma unroll
    for (int i = 0; i < 2; i++)
#pragma unroll
        for (int j = 0; j < 2; j++) {
            wmma::store_matrix_sync(st, acc[i][j], 16, wmma::mem_row_major);
            __syncwarp();
            tile_to_half(st, outh, n0 + wr * 32 + i * 16,
                         wc * 32 + j * 16, C2, lane);
            __syncwarp();
        }
}

// ---- helpers ----
__device__ __forceinline__ float4 ld_half4(const __half* base, int idx4) {
    uint2 u = __ldg((const uint2*)base + idx4);
    __half2 ha = *(__half2*)&u.x, hb = *(__half2*)&u.y;
    float2 fa = __half22float2(ha), fb = __half22float2(hb);
    return make_float4(fa.x, fa.y, fb.x, fb.y);
}
__device__ __forceinline__ float lrelu_dot(float4 L, float4 R, float e0, float e1,
                                           float4 W0, float4 W1_, float4 A) {
    float zx = L.x + R.x + e0 * W0.x + e1 * W1_.x; zx = zx > 0.f ? zx : 0.2f * zx;
    float zy = L.y + R.y + e0 * W0.y + e1 * W1_.y; zy = zy > 0.f ? zy : 0.2f * zy;
    float zz = L.z + R.z + e0 * W0.z + e1 * W1_.z; zz = zz > 0.f ? zz : 0.2f * zz;
    float zw = L.w + R.w + e0 * W0.w + e1 * W1_.w; zw = zw > 0.f ? zw : 0.2f * zw;
    return A.x * zx + A.y * zy + A.z * zz + A.w * zw;
}

// ---------------- layer-1 SINGLE-PASS fused attention+aggregation (node chunk) ----------------
__global__ void __launch_bounds__(128) k_edge1(const float* __restrict__ W1e,
                                               const float* __restrict__ att,
                                               const float* __restrict__ b1, int ns, int N) {
    int d = ns + blockIdx.x;
    int lane = threadIdx.x & 31, h = threadIdx.x >> 5;
    int c4 = h * 32 + lane;
    float4 R  = ld_half4(g_xr1h + (long)d * C1, c4);
    float4 W0 = __ldg((const float4*)W1e + c4);
    float4 W1_ = __ldg((const float4*)(W1e + C1) + c4);
    float4 A  = __ldg((const float4*)att + c4);
    int rs = g_rowstart[d], re = g_rowstart[d + 1];
    float den;
    float4 acc;
    {   // self loop
        float e0 = g_loopea[2 * d], e1 = g_loopea[2 * d + 1];
        float4 L = ld_half4(g_xl1h + (long)d * C1, c4);
        float part = lrelu_dot(L, R, e0, e1, W0, W1_, A);
#pragma unroll
        for (int o = 16; o > 0; o >>= 1) part += __shfl_xor_sync(0xffffffffu, part, o);
        float p = __expf(part);
        den = p;
        acc.x = p * L.x; acc.y = p * L.y; acc.z = p * L.z; acc.w = p * L.w;
    }
    int i = rs;
    for (; i + 4 <= re; i += 4) {
        int s0 = __ldg(g_esrc + i), s1 = __ldg(g_esrc + i + 1);
        int s2 = __ldg(g_esrc + i + 2), s3 = __ldg(g_esrc + i + 3);
        float2 ea0 = __ldg(g_eea + i), ea1 = __ldg(g_eea + i + 1);
        float2 ea2 = __ldg(g_eea + i + 2), ea3 = __ldg(g_eea + i + 3);
        float4 L0 = ld_half4(g_xl1h + (long)s0 * C1, c4);
        float4 L1 = ld_half4(g_xl1h + (long)s1 * C1, c4);
        float4 L2 = ld_half4(g_xl1h + (long)s2 * C1, c4);
        float4 L3 = ld_half4(g_xl1h + (long)s3 * C1, c4);
        float p0 = lrelu_dot(L0, R, ea0.x, ea0.y, W0, W1_, A);
        float p1 = lrelu_dot(L1, R, ea1.x, ea1.y, W0, W1_, A);
        float p2 = lrelu_dot(L2, R, ea2.x, ea2.y, W0, W1_, A);
        float p3 = lrelu_dot(L3, R, ea3.x, ea3.y, W0, W1_, A);
#pragma unroll
        for (int o = 16; o > 0; o >>= 1) {
            p0 += __shfl_xor_sync(0xffffffffu, p0, o);
            p1 += __shfl_xor_sync(0xffffffffu, p1, o);
            p2 += __shfl_xor_sync(0xffffffffu, p2, o);
            p3 += __shfl_xor_sync(0xffffffffu, p3, o);
        }
        p0 = __expf(p0); p1 = __expf(p1); p2 = __expf(p2); p3 = __expf(p3);
        den += (p0 + p1) + (p2 + p3);
        acc.x = fmaf(p0, L0.x, fmaf(p1, L1.x, fmaf(p2, L2.x, fmaf(p3, L3.x, acc.x))));
        acc.y = fmaf(p0, L0.y, fmaf(p1, L1.y, fmaf(p2, L2.y, fmaf(p3, L3.y, acc.y))));
        acc.z = fmaf(p0, L0.z, fmaf(p1, L1.z, fmaf(p2, L2.z, fmaf(p3, L3.z, acc.z))));
        acc.w = fmaf(p0, L0.w, fmaf(p1, L1.w, fmaf(p2, L2.w, fmaf(p3, L3.w, acc.w))));
    }
    for (; i < re; i++) {
        int s0 = __ldg(g_esrc + i);
        float2 ea0 = __ldg(g_eea + i);
        float4 L0 = ld_half4(g_xl1h + (long)s0 * C1, c4);
        float p0 = lrelu_dot(L0, R, ea0.x, ea0.y, W0, W1_, A);
#pragma unroll
        for (int o = 16; o > 0; o >>= 1) p0 += __shfl_xor_sync(0xffffffffu, p0, o);
        p0 = __expf(p0);
        den += p0;
        acc.x = fmaf(p0, L0.x, acc.x); acc.y = fmaf(p0, L0.y, acc.y);
        acc.z = fmaf(p0, L0.z, acc.z); acc.w = fmaf(p0, L0.w, acc.w);
    }
    float inv = 1.f / den;
    float4 bb = __ldg((const float4*)b1 + c4);
    float v0 = acc.x * inv + bb.x; v0 = v0 > 0.f ? v0 : (__expf(v0) - 1.f);
    float v1 = acc.y * inv + bb.y; v1 = v1 > 0.f ? v1 : (__expf(v1) - 1.f);
    float v2 = acc.z * inv + bb.z; v2 = v2 > 0.f ? v2 : (__expf(v2) - 1.f);
    float v3 = acc.w * inv + bb.w; v3 = v3 > 0.f ? v3 : (__expf(v3) - 1.f);
    __half2 hA = __floats2half2_rn(v0, v1);
    __half2 hB = __floats2half2_rn(v2, v3);
    uint2 u = make_uint2(*(unsigned*)&hA, *(unsigned*)&hB);
    ((uint2*)(g_h1h + (long)d * C1))[c4] = u;
}

// ---------------- layer-2 SINGLE-PASS fused att+agg+ELU+FC: warp per node ----------------
__global__ void __launch_bounds__(256) k_edge2(const float* __restrict__ W2e,
                                               const float* __restrict__ att2,
                                               const float* __restrict__ b2,
                                               const float* __restrict__ Wfc,
                                               const float* __restrict__ bfc,
                                               float* __restrict__ out, int N) {
    int w = threadIdx.x >> 5, lane = threadIdx.x & 31;
    int node = blockIdx.x * 8 + w;
    if (node >= N) return;
    float4 R  = ld_half4(g_xr2h + (long)node * C2, lane);
    float4 W0 = __ldg((const float4*)W2e + lane);
    float4 W1_ = __ldg((const float4*)(W2e + C2) + lane);
    float4 A  = __ldg((const float4*)att2 + lane);
    int rs = g_rowstart[node], re = g_rowstart[node + 1];
    float den;
    float4 acc;
    {
        float e0 = g_loopea[2 * node], e1 = g_loopea[2 * node + 1];
        float4 L = ld_half4(g_xl2h + (long)node * C2, lane);
        float part = lrelu_dot(L, R, e0, e1, W0, W1_, A);
#pragma unroll
        for (int o = 16; o > 0; o >>= 1) part += __shfl_xor_sync(0xffffffffu, part, o);
        float p = __expf(part);
        den = p;
        acc.x = p * L.x; acc.y = p * L.y; acc.z = p * L.z; acc.w = p * L.w;
    }
    int i = rs;
    for (; i + 4 <= re; i += 4) {
        int s0 = __ldg(g_esrc + i), s1 = __ldg(g_esrc + i + 1);
        int s2 = __ldg(g_esrc + i + 2), s3 = __ldg(g_esrc + i + 3);
        float2 ea0 = __ldg(g_eea + i), ea1 = __ldg(g_eea + i + 1);
        float2 ea2 = __ldg(g_eea + i + 2), ea3 = __ldg(g_eea + i + 3);
        float4 L0 = ld_half4(g_xl2h + (long)s0 * C2, lane);
        float4 L1 = ld_half4(g_xl2h + (long)s1 * C2, lane);
        float4 L2 = ld_half4(g_xl2h + (long)s2 * C2, lane);
        float4 L3 = ld_half4(g_xl2h + (long)s3 * C2, lane);
        float p0 = lrelu_dot(L0, R, ea0.x, ea0.y, W0, W1_, A);
        float p1 = lrelu_dot(L1, R, ea1.x, ea1.y, W0, W1_, A);
        float p2 = lrelu_dot(L2, R, ea2.x, ea2.y, W0, W1_, A);
        float p3 = lrelu_dot(L3, R, ea3.x, ea3.y, W0, W1_, A);
#pragma unroll
        for (int o = 16; o > 0; o >>= 1) {
            p0 += __shfl_xor_sync(0xffffffffu, p0, o);
            p1 += __shfl_xor_sync(0xffffffffu, p1, o);
            p2 += __shfl_xor_sync(0xffffffffu, p2, o);
            p3 += __shfl_xor_sync(0xffffffffu, p3, o);
        }
        p0 = __expf(p0); p1 = __expf(p1); p2 = __expf(p2); p3 = __expf(p3);
        den += (p0 + p1) + (p2 + p3);
        acc.x = fmaf(p0, L0.x, fmaf(p1, L1.x, fmaf(p2, L2.x, fmaf(p3, L3.x, acc.x))));
        acc.y = fmaf(p0, L0.y, fmaf(p1, L1.y, fmaf(p2, L2.y, fmaf(p3, L3.y, acc.y))));
        acc.z = fmaf(p0, L0.z, fmaf(p1, L1.z, fmaf(p2, L2.z, fmaf(p3, L3.z, acc.z))));
        acc.w = fmaf(p0, L0.w, fmaf(p1, L1.w, fmaf(p2, L2.w, fmaf(p3, L3.w, acc.w))));
    }
    for (; i < re; i++) {
        int s0 = __ldg(g_esrc + i);
        float2 ea0 = __ldg(g_eea + i);
        float4 L0 = ld_half4(g_xl2h + (long)s0 * C2, lane);
        float p0 = lrelu_dot(L0, R, ea0.x, ea0.y, W0, W1_, A);
#pragma unroll
        for (int o = 16; o > 0; o >>= 1) p0 += __shfl_xor_sync(0xffffffffu, p0, o);
        p0 = __expf(p0);
        den += p0;
        acc.x = fmaf(p0, L0.x, acc.x); acc.y = fmaf(p0, L0.y, acc.y);
        acc.z = fmaf(p0, L0.z, acc.z); acc.w = fmaf(p0, L0.w, acc.w);
    }
    float inv = 1.f / den;
    float4 bb = __ldg((const float4*)b2 + lane);
    float v0 = acc.x * inv + bb.x; v0 = v0 > 0.f ? v0 : (__expf(v0) - 1.f);
    float v1 = acc.y * inv + bb.y; v1 = v1 > 0.f ? v1 : (__expf(v1) - 1.f);
    float v2 = acc.z * inv + bb.z; v2 = v2 > 0.f ? v2 : (__expf(v2) - 1.f);
    float v3 = acc.w * inv + bb.w; v3 = v3 > 0.f ? v3 : (__expf(v3) - 1.f);
    float4 wA = __ldg((const float4*)Wfc + 2 * lane);
    float4 wB = __ldg((const float4*)Wfc + 2 * lane + 1);
    float o0 = v0 * wA.x + v1 * wA.z + v2 * wB.x + v3 * wB.z;
    float o1 = v0 * wA.y + v1 * wA.w + v2 * wB.y + v3 * wB.w;
#pragma unroll
    for (int o = 16; o > 0; o >>= 1) {
        o0 += __shfl_xor_sync(0xffffffffu, o0, o);
        o1 += __shfl_xor_sync(0xffffffffu, o1, o);
    }
    if (lane == 0) {
        out[2 * node]     = o0 + __ldg(bfc);
        out[2 * node + 1] = o1 + __ldg(bfc + 1);
    }
}

// ---------------- launch ----------------
extern "C" void kernel_launch(void* const* d_in, const int* in_sizes, int n_in,
                              void* d_out, int out_size) {
    const float* x    = (const float*)d_in[0];
    const int*   ei   = (const int*)  d_in[1];
    const float* ea   = (const float*)d_in[2];
    const int*   rt   = (const int*)  d_in[3];
    const float* aaem = (const float*)d_in[4];
    const float* W1l  = (const float*)d_in[5];
    const float* W1r  = (const float*)d_in[6];
    const float* W1e  = (const float*)d_in[7];
    const float* att1 = (const float*)d_in[8];
    const float* b1   = (const float*)d_in[9];
    const float* W2l  = (const float*)d_in[10];
    const float* W2r  = (const float*)d_in[11];
    const float* W2e  = (const float*)d_in[12];
    const float* att2 = (const float*)d_in[13];
    const float* b2   = (const float*)d_in[14];
    const float* Wfc  = (const float*)d_in[15];
    const float* bfc  = (const float*)d_in[16];
    float* out = (float*)d_out;

    int N = in_sizes[0] / 5;
    int E = in_sizes[1] / 2;
    if (N > MAXN) N = MAXN;
    if (E > MAXE) E = MAXE;
    const int* src = ei;
    const int* dst = ei + E;
    int NP_BLK = (N + 63) / 64;
    int nb = (N + 1023) / 1024;

    // lazily-created side stream + fork/join events (host resources, no device mem)
    static bool s_init = false;
    static cudaStream_t sB;
    static cudaEvent_t evF, evJ, evG;
    static cudaEvent_t evC[NCHUNK];
    if (!s_init) {
        cudaStreamCreateWithFlags(&sB, cudaStreamNonBlocking);
        cudaEventCreateWithFlags(&evF, cudaEventDisableTiming);
        cudaEventCreateWithFlags(&evJ, cudaEventDisableTiming);
        cudaEventCreateWithFlags(&evG, cudaEventDisableTiming);
        for (int c = 0; c < NCHUNK; c++)
            cudaEventCreateWithFlags(&evC[c], cudaEventDisableTiming);
        s_init = true;
    }

    // fork: preprocessing chain (edge data) on sB, concurrent with h0h+gemm1 (feature data)
    cudaEventRecord(evF, 0);
    cudaStreamWaitEvent(sB, evF, 0);
    k_init<<<(N + 255) / 256, 256, 0, sB>>>(N);
    k_deg<<<(E + 255) / 256, 256, 0, sB>>>(dst, ea, E);
    k_scan1<<<nb, 1024, 0, sB>>>(N);
    k_scan3<<<(N + 255) / 256, 256, 0, sB>>>(N, nb);
    k_scatter<<<(E + 255) / 256, 256, 0, sB>>>(src, dst, ea, E);
    cudaEventRecord(evJ, sB);

    k_h0h<<<(N * 6 + 255) / 256, 256>>>(x, rt, aaem, N);
    k_gemm1<<<dim3(NP_BLK, 4, 2), 256>>>(W1l, W1r, N);

    // join: edge1 needs both gemm1 outputs and CSR/loopea
    cudaStreamWaitEvent(0, evJ, 0);

    // 2-chunk pipeline: gemm2 for chunk c runs on sB while edge1 chunk c+1 runs on 0
    int CHUNK = (((N + NCHUNK - 1) / NCHUNK + 63) / 64) * 64;
    for (int c = 0; c < NCHUNK; c++) {
        int ns = c * CHUNK;
        int cnt = N - ns; if (cnt > CHUNK) cnt = CHUNK;
        if (cnt <= 0) break;
        k_edge1<<<cnt, 128>>>(W1e, att1, b1, ns, N);
        cudaEventRecord(evC[c], 0);
        cudaStreamWaitEvent(sB, evC[c], 0);
        k_gemm2<<<dim3((cnt + 63) / 64, 1, 2), 256, 0, sB>>>(W2l, W2r, ns, N);
    }
    cudaEventRecord(evG, sB);
    cudaStreamWaitEvent(0, evG, 0);

    k_edge2<<<(N + 7) / 8, 256>>>(W2e, att2, b2, Wfc, bfc, out, N);
}

// round 17
// speedup vs baseline: 1.0495x; 1.0495x over previous
#include <cuda_runtime.h>
#include <cuda_fp16.h>
#include <mma.h>
#include <math.h>
#include <float.h>

using namespace nvcuda;

#define MAXN 20000
#define MAXNP 20032
#define MAXE 150000
#define C1 512
#define H1 4
#define C2 128
#define K1P 48

// ---------------- scratch ----------------
static __device__ __half g_h0h[MAXNP * K1P];   // fp16 concat(x, aa_emb[rt]), padded to 48
static __device__ __half g_xl1h[MAXNP * C1];   // gather-side features, fp16
static __device__ __half g_xr1h[MAXNP * C1];   // dst-side features, fp16
static __device__ __half g_h1h[MAXNP * C1];    // layer-1 output, fp16 (gemm2 A operand)
static __device__ __half g_xl2h[MAXNP * C2];
static __device__ __half g_xr2h[MAXNP * C2];
static __device__ float  g_easum[MAXN * 2];
static __device__ float  g_loopea[MAXN * 2];
static __device__ int    g_deg[MAXN];
static __device__ int    g_rowstart[MAXN];     // block-local exclusive (scan1 output)
static __device__ int    g_rowfin[MAXN + 1];   // finalized row pointers (edge kernels use this)
static __device__ int    g_cursor[MAXN];
static __device__ int    g_esrc[MAXE];         // src permuted into CSR order
static __device__ float2 g_eea[MAXE];          // edge_attr permuted into CSR order
static __device__ int    g_blocksum[32];

// ---------------- per-node init ----------------
__global__ void k_init(int N) {
    int i = blockIdx.x * blockDim.x + threadIdx.x;
    if (i >= N) return;
    g_deg[i] = 0;
    g_cursor[i] = 0;
    g_easum[2 * i] = 0.f;
    g_easum[2 * i + 1] = 0.f;
}

// ---------------- fp16 h0 = concat(x, aa_emb[rt]) padded to 48; one uint4 per thread ----------------
__global__ void k_h0h(const float* __restrict__ x, const int* __restrict__ rt,
                      const float* __restrict__ aaemb, int N) {
    int idx = blockIdx.x * blockDim.x + threadIdx.x;   // N*6 uint4 groups
    if (idx >= N * 6) return;
    int n = idx / 6, g = idx - n * 6;
    int c0 = g * 8;
    int r = __ldg(rt + n);
    __half h[8];
#pragma unroll
    for (int j = 0; j < 8; j++) {
        int c = c0 + j;
        float v = 0.f;
        if (c < 5) v = __ldg(x + n * 5 + c);
        else if (c < 37) v = __ldg(aaemb + r * 32 + (c - 5));
        h[j] = __float2half(v);
    }
    *(uint4*)(g_h0h + (long)n * K1P + c0) = *(uint4*)h;
}

// ---------------- degree + edge-attr sums ----------------
__global__ void k_deg(const int* __restrict__ dst, const float* __restrict__ ea, int E) {
    int e = blockIdx.x * blockDim.x + threadIdx.x;
    if (e >= E) return;
    int d = dst[e];
    float2 a = ((const float2*)ea)[e];
    atomicAdd(&g_deg[d], 1);
    atomicAdd(&g_easum[2 * d], a.x);
    atomicAdd(&g_easum[2 * d + 1], a.y);
}

// ---------------- per-1024-block scan ----------------
__global__ void k_scan1(int N) {
    __shared__ int sm[1024];
    int i = blockIdx.x * 1024 + threadIdx.x;
    int v = (i < N) ? g_deg[i] : 0;
    sm[threadIdx.x] = v;
    __syncthreads();
    for (int o = 1; o < 1024; o <<= 1) {
        int t = (threadIdx.x >= o) ? sm[threadIdx.x - o] : 0;
        __syncthreads();
        sm[threadIdx.x] += t;
        __syncthreads();
    }
    if (i < N) g_rowstart[i] = sm[threadIdx.x] - v;
    if (threadIdx.x == 1023) g_blocksum[blockIdx.x] = sm[1023];
}

// ---------------- fused finalize + scatter ----------------
// Every block recomputes the <=32-element block-offset scan in smem (cheap).
// Threads with idx < N+1 finalize g_rowfin (+ loopea for idx < N);
// threads with idx < E scatter their edge. No read-modify-write races:
// scatter reads only g_rowstart (block-local) + soff, never g_rowfin.
__global__ void k_scatter(const int* __restrict__ src, const int* __restrict__ dst,
                          const float* __restrict__ ea, int E, int N, int nb, int total) {
    __shared__ int soff[32];
    int t = threadIdx.x;
    if (t < 32) {
        int v = (t < nb) ? g_blocksum[t] : 0;
        int s = v;
#pragma unroll
        for (int o = 1; o < 32; o <<= 1) {
            int u = __shfl_up_sync(0xffffffffu, s, o);
            if (t >= o) s += u;
        }
        soff[t] = s - v;   // exclusive block offsets
    }
    __syncthreads();
    int idx = blockIdx.x * blockDim.x + t;
    if (idx < N) {
        g_rowfin[idx] = g_rowstart[idx] + soff[idx >> 10];
        int dg = g_deg[idx];
        float fd = (dg < 1) ? 1.f : (float)dg;
        g_loopea[2 * idx]     = g_easum[2 * idx] / fd;
        g_loopea[2 * idx + 1] = g_easum[2 * idx + 1] / fd;
    }
    if (idx == N) g_rowfin[N] = total;   // == E
    if (idx < E) {
        int d = __ldg(dst + idx);
        int pos = g_rowstart[d] + soff[d >> 10] + atomicAdd(&g_cursor[d], 1);
        g_esrc[pos] = __ldg(src + idx);
        g_eea[pos] = __ldg((const float2*)ea + idx);
    }
}

// ---- epilogue helper: warp writes one 16x16 fp32 tile (ldm=16) as fp16 (16B stores) ----
__device__ __forceinline__ void tile_to_half(const float* st, __half* gbase,
                                             long grow0, int gcol0, int ldg_, int lane) {
    int row = lane >> 1, colh = (lane & 1) * 8;
    const float* sp = st + row * 16 + colh;
    __half2 h0 = __floats2half2_rn(sp[0], sp[1]);
    __half2 h1 = __floats2half2_rn(sp[2], sp[3]);
    __half2 h2 = __floats2half2_rn(sp[4], sp[5]);
    __half2 h3 = __floats2half2_rn(sp[6], sp[7]);
    uint4 u = make_uint4(*(unsigned*)&h0, *(unsigned*)&h1, *(unsigned*)&h2, *(unsigned*)&h3);
    *(uint4*)(gbase + (grow0 + row) * ldg_ + gcol0 + colh) = u;
}

// ---------------- layer-1 GEMM (fp16 WMMA m16n16k16): h0h[NP,48] @ [48,512] ----------------
__global__ void __launch_bounds__(256) k_gemm1(const float* __restrict__ Wl,
                                               const float* __restrict__ Wr, int N) {
    const float* W = blockIdx.z ? Wr : Wl;
    __half* outh = blockIdx.z ? g_xr1h : g_xl1h;
    __shared__ __half Ah[64 * 56];
    __shared__ __half Bh[K1P * 136];
    __shared__ float stg[8 * 256];
    int tid = threadIdx.x;
    int n0 = blockIdx.x * 64;
    int col0 = blockIdx.y * 128;
    for (int idx = tid; idx < 64 * 6; idx += 256) {
        int r = idx / 6, g = idx - r * 6;
        uint4 u = make_uint4(0, 0, 0, 0);
        if (n0 + r < N) u = *(const uint4*)(g_h0h + (long)(n0 + r) * K1P + g * 8);
        *(uint4*)(Ah + r * 56 + g * 8) = u;
    }
    for (int idx = tid; idx < K1P * 128; idx += 256) {
        int r = idx >> 7, c = idx & 127;
        float v = (r < 37) ? W[r * C1 + col0 + c] : 0.f;
        Bh[r * 136 + c] = __float2half(v);
    }
    __syncthreads();
    int wid = tid >> 5, lane = tid & 31;
    int wr = wid & 1, wc = wid >> 1;
    wmma::fragment<wmma::accumulator, 16, 16, 16, float> acc[2][2];
#pragma unroll
    for (int i = 0; i < 2; i++)
#pragma unroll
        for (int j = 0; j < 2; j++) wmma::fill_fragment(acc[i][j], 0.f);
#pragma unroll
    for (int kk = 0; kk < K1P; kk += 16) {
        wmma::fragment<wmma::matrix_a, 16, 16, 16, __half, wmma::row_major> a[2];
        wmma::fragment<wmma::matrix_b, 16, 16, 16, __half, wmma::row_major> b[2];
#pragma unroll
        for (int i = 0; i < 2; i++)
            wmma::load_matrix_sync(a[i], &Ah[(wr * 32 + i * 16) * 56 + kk], 56);
#pragma unroll
        for (int j = 0; j < 2; j++)
            wmma::load_matrix_sync(b[j], &Bh[kk * 136 + wc * 32 + j * 16], 136);
#pragma unroll
        for (int i = 0; i < 2; i++)
#pragma unroll
            for (int j = 0; j < 2; j++)
                wmma::mma_sync(acc[i][j], a[i], b[j], acc[i][j]);
    }
    float* st = stg + wid * 256;
#pragma unroll
    for (int i = 0; i < 2; i++)
#pragma unroll
        for (int j = 0; j < 2; j++) {
            wmma::store_matrix_sync(st, acc[i][j], 16, wmma::mem_row_major);
            __syncwarp();
            tile_to_half(st, outh, n0 + wr * 32 + i * 16,
                         col0 + wc * 32 + j * 16, C1, lane);
            __syncwarp();
        }
}

// ---------------- layer-2 GEMM (fp16 WMMA m16n16k16): h1h[NP,512] @ [512,128] ----------------
__global__ void __launch_bounds__(256) k_gemm2(const float* __restrict__ Wl,
                                               const float* __restrict__ Wr, int N) {
    const float* W = blockIdx.z ? Wr : Wl;
    __half* outh = blockIdx.z ? g_xr2h : g_xl2h;
    __shared__ __half Ah[64 * 40];
    __shared__ __half Bh[32 * 136];
    __shared__ float stg[8 * 256];
    int tid = threadIdx.x;
    int n0 = blockIdx.x * 64;
    int wid = tid >> 5, lane = tid & 31;
    int wr = wid & 1, wc = wid >> 1;
    wmma::fragment<wmma::accumulator, 16, 16, 16, float> acc[2][2];
#pragma unroll
    for (int i = 0; i < 2; i++)
#pragma unroll
        for (int j = 0; j < 2; j++) wmma::fill_fragment(acc[i][j], 0.f);
    for (int k0 = 0; k0 < C1; k0 += 32) {
        {   // A: 64x32 halves, one uint4 (8 halves) per thread
            int r = tid >> 2, g = (tid & 3) * 8;
            uint4 u = make_uint4(0, 0, 0, 0);
            if (n0 + r < N)
                u = *(const uint4*)(g_h1h + (long)(n0 + r) * C1 + k0 + g);
            *(uint4*)(Ah + r * 40 + g) = u;
        }
        for (int idx = tid; idx < 32 * 128; idx += 256) {
            int r = idx >> 7, c = idx & 127;
            Bh[r * 136 + c] = __float2half(W[(k0 + r) * C2 + c]);
        }
        __syncthreads();
#pragma unroll
        for (int kk = 0; kk < 32; kk += 16) {
            wmma::fragment<wmma::matrix_a, 16, 16, 16, __half, wmma::row_major> a[2];
            wmma::fragment<wmma::matrix_b, 16, 16, 16, __half, wmma::row_major> b[2];
#pragma unroll
            for (int i = 0; i < 2; i++)
                wmma::load_matrix_sync(a[i], &Ah[(wr * 32 + i * 16) * 40 + kk], 40);
#pragma unroll
            for (int j = 0; j < 2; j++)
                wmma::load_matrix_sync(b[j], &Bh[kk * 136 + wc * 32 + j * 16], 136);
#pragma unroll
            for (int i = 0; i < 2; i++)
#pragma unroll
                for (int j = 0; j < 2; j++)
                    wmma::mma_sync(acc[i][j], a[i], b[j], acc[i][j]);
        }
        __syncthreads();
    }
    float* st = stg + wid * 256;
#pragma unroll
    for (int i = 0; i < 2; i++)
#pragma unroll
        for (int j = 0; j < 2; j++) {
            wmma::store_matrix_sync(st, acc[i][j], 16, wmma::mem_row_major);
            __syncwarp();
            tile_to_half(st, outh, n0 + wr * 32 + i * 16,
                         wc * 32 + j * 16, C2, lane);
            __syncwarp();
        }
}

// ---- helpers ----
__device__ __forceinline__ float4 ld_half4(const __half* base, int idx4) {
    uint2 u = __ldg((const uint2*)base + idx4);
    __half2 ha = *(__half2*)&u.x, hb = *(__half2*)&u.y;
    float2 fa = __half22float2(ha), fb = __half22float2(hb);
    return make_float4(fa.x, fa.y, fb.x, fb.y);
}
__device__ __forceinline__ float lrelu_dot(float4 L, float4 R, float e0, float e1,
                                           float4 W0, float4 W1_, float4 A) {
    float zx = L.x + R.x + e0 * W0.x + e1 * W1_.x; zx = zx > 0.f ? zx : 0.2f * zx;
    float zy = L.y + R.y + e0 * W0.y + e1 * W1_.y; zy = zy > 0.f ? zy : 0.2f * zy;
    float zz = L.z + R.z + e0 * W0.z + e1 * W1_.z; zz = zz > 0.f ? zz : 0.2f * zz;
    float zw = L.w + R.w + e0 * W0.w + e1 * W1_.w; zw = zw > 0.f ? zw : 0.2f * zw;
    return A.x * zx + A.y * zy + A.z * zz + A.w * zw;
}

// ---------------- layer-1 SINGLE-PASS fused attention+aggregation ----------------
__global__ void __launch_bounds__(128) k_edge1(const float* __restrict__ W1e,
                                               const float* __restrict__ att,
                                               const float* __restrict__ b1, int N) {
    int d = blockIdx.x;
    int lane = threadIdx.x & 31, h = threadIdx.x >> 5;
    int c4 = h * 32 + lane;
    float4 R  = ld_half4(g_xr1h + (long)d * C1, c4);
    float4 W0 = __ldg((const float4*)W1e + c4);
    float4 W1_ = __ldg((const float4*)(W1e + C1) + c4);
    float4 A  = __ldg((const float4*)att + c4);
    int rs = g_rowfin[d], re = g_rowfin[d + 1];
    float den;
    float4 acc;
    {   // self loop
        float e0 = g_loopea[2 * d], e1 = g_loopea[2 * d + 1];
        float4 L = ld_half4(g_xl1h + (long)d * C1, c4);
        float part = lrelu_dot(L, R, e0, e1, W0, W1_, A);
#pragma unroll
        for (int o = 16; o > 0; o >>= 1) part += __shfl_xor_sync(0xffffffffu, part, o);
        float p = __expf(part);
        den = p;
        acc.x = p * L.x; acc.y = p * L.y; acc.z = p * L.z; acc.w = p * L.w;
    }
    int i = rs;
    for (; i + 4 <= re; i += 4) {
        int s0 = __ldg(g_esrc + i), s1 = __ldg(g_esrc + i + 1);
        int s2 = __ldg(g_esrc + i + 2), s3 = __ldg(g_esrc + i + 3);
        float2 ea0 = __ldg(g_eea + i), ea1 = __ldg(g_eea + i + 1);
        float2 ea2 = __ldg(g_eea + i + 2), ea3 = __ldg(g_eea + i + 3);
        float4 L0 = ld_half4(g_xl1h + (long)s0 * C1, c4);
        float4 L1 = ld_half4(g_xl1h + (long)s1 * C1, c4);
        float4 L2 = ld_half4(g_xl1h + (long)s2 * C1, c4);
        float4 L3 = ld_half4(g_xl1h + (long)s3 * C1, c4);
        float p0 = lrelu_dot(L0, R, ea0.x, ea0.y, W0, W1_, A);
        float p1 = lrelu_dot(L1, R, ea1.x, ea1.y, W0, W1_, A);
        float p2 = lrelu_dot(L2, R, ea2.x, ea2.y, W0, W1_, A);
        float p3 = lrelu_dot(L3, R, ea3.x, ea3.y, W0, W1_, A);
#pragma unroll
        for (int o = 16; o > 0; o >>= 1) {
            p0 += __shfl_xor_sync(0xffffffffu, p0, o);
            p1 += __shfl_xor_sync(0xffffffffu, p1, o);
            p2 += __shfl_xor_sync(0xffffffffu, p2, o);
            p3 += __shfl_xor_sync(0xffffffffu, p3, o);
        }
        p0 = __expf(p0); p1 = __expf(p1); p2 = __expf(p2); p3 = __expf(p3);
        den += (p0 + p1) + (p2 + p3);
        acc.x = fmaf(p0, L0.x, fmaf(p1, L1.x, fmaf(p2, L2.x, fmaf(p3, L3.x, acc.x))));
        acc.y = fmaf(p0, L0.y, fmaf(p1, L1.y, fmaf(p2, L2.y, fmaf(p3, L3.y, acc.y))));
        acc.z = fmaf(p0, L0.z, fmaf(p1, L1.z, fmaf(p2, L2.z, fmaf(p3, L3.z, acc.z))));
        acc.w = fmaf(p0, L0.w, fmaf(p1, L1.w, fmaf(p2, L2.w, fmaf(p3, L3.w, acc.w))));
    }
    for (; i < re; i++) {
        int s0 = __ldg(g_esrc + i);
        float2 ea0 = __ldg(g_eea + i);
        float4 L0 = ld_half4(g_xl1h + (long)s0 * C1, c4);
        float p0 = lrelu_dot(L0, R, ea0.x, ea0.y, W0, W1_, A);
#pragma unroll
        for (int o = 16; o > 0; o >>= 1) p0 += __shfl_xor_sync(0xffffffffu, p0, o);
        p0 = __expf(p0);
        den += p0;
        acc.x = fmaf(p0, L0.x, acc.x); acc.y = fmaf(p0, L0.y, acc.y);
        acc.z = fmaf(p0, L0.z, acc.z); acc.w = fmaf(p0, L0.w, acc.w);
    }
    float inv = 1.f / den;
    float4 bb = __ldg((const float4*)b1 + c4);
    float v0 = acc.x * inv + bb.x; v0 = v0 > 0.f ? v0 : (__expf(v0) - 1.f);
    float v1 = acc.y * inv + bb.y; v1 = v1 > 0.f ? v1 : (__expf(v1) - 1.f);
    float v2 = acc.z * inv + bb.z; v2 = v2 > 0.f ? v2 : (__expf(v2) - 1.f);
    float v3 = acc.w * inv + bb.w; v3 = v3 > 0.f ? v3 : (__expf(v3) - 1.f);
    __half2 hA = __floats2half2_rn(v0, v1);
    __half2 hB = __floats2half2_rn(v2, v3);
    uint2 u = make_uint2(*(unsigned*)&hA, *(unsigned*)&hB);
    ((uint2*)(g_h1h + (long)d * C1))[c4] = u;
}

// ---------------- layer-2 SINGLE-PASS fused att+agg+ELU+FC: warp per node ----------------
__global__ void __launch_bounds__(256) k_edge2(const float* __restrict__ W2e,
                                               const float* __restrict__ att2,
                                               const float* __restrict__ b2,
                                               const float* __restrict__ Wfc,
                                               const float* __restrict__ bfc,
                                               float* __restrict__ out, int N) {
    int w = threadIdx.x >> 5, lane = threadIdx.x & 31;
    int node = blockIdx.x * 8 + w;
    if (node >= N) return;
    float4 R  = ld_half4(g_xr2h + (long)node * C2, lane);
    float4 W0 = __ldg((const float4*)W2e + lane);
    float4 W1_ = __ldg((const float4*)(W2e + C2) + lane);
    float4 A  = __ldg((const float4*)att2 + lane);
    int rs = g_rowfin[node], re = g_rowfin[node + 1];
    float den;
    float4 acc;
    {
        float e0 = g_loopea[2 * node], e1 = g_loopea[2 * node + 1];
        float4 L = ld_half4(g_xl2h + (long)node * C2, lane);
        float part = lrelu_dot(L, R, e0, e1, W0, W1_, A);
#pragma unroll
        for (int o = 16; o > 0; o >>= 1) part += __shfl_xor_sync(0xffffffffu, part, o);
        float p = __expf(part);
        den = p;
        acc.x = p * L.x; acc.y = p * L.y; acc.z = p * L.z; acc.w = p * L.w;
    }
    int i = rs;
    for (; i + 4 <= re; i += 4) {
        int s0 = __ldg(g_esrc + i), s1 = __ldg(g_esrc + i + 1);
        int s2 = __ldg(g_esrc + i + 2), s3 = __ldg(g_esrc + i + 3);
        float2 ea0 = __ldg(g_eea + i), ea1 = __ldg(g_eea + i + 1);
        float2 ea2 = __ldg(g_eea + i + 2), ea3 = __ldg(g_eea + i + 3);
        float4 L0 = ld_half4(g_xl2h + (long)s0 * C2, lane);
        float4 L1 = ld_half4(g_xl2h + (long)s1 * C2, lane);
        float4 L2 = ld_half4(g_xl2h + (long)s2 * C2, lane);
        float4 L3 = ld_half4(g_xl2h + (long)s3 * C2, lane);
        float p0 = lrelu_dot(L0, R, ea0.x, ea0.y, W0, W1_, A);
        float p1 = lrelu_dot(L1, R, ea1.x, ea1.y, W0, W1_, A);
        float p2 = lrelu_dot(L2, R, ea2.x, ea2.y, W0, W1_, A);
        float p3 = lrelu_dot(L3, R, ea3.x, ea3.y, W0, W1_, A);
#pragma unroll
        for (int o = 16; o > 0; o >>= 1) {
            p0 += __shfl_xor_sync(0xffffffffu, p0, o);
            p1 += __shfl_xor_sync(0xffffffffu, p1, o);
            p2 += __shfl_xor_sync(0xffffffffu, p2, o);
            p3 += __shfl_xor_sync(0xffffffffu, p3, o);
        }
        p0 = __expf(p0); p1 = __expf(p1); p2 = __expf(p2); p3 = __expf(p3);
        den += (p0 + p1) + (p2 + p3);
        acc.x = fmaf(p0, L0.x, fmaf(p1, L1.x, fmaf(p2, L2.x, fmaf(p3, L3.x, acc.x))));
        acc.y = fmaf(p0, L0.y, fmaf(p1, L1.y, fmaf(p2, L2.y, fmaf(p3, L3.y, acc.y))));
        acc.z = fmaf(p0, L0.z, fmaf(p1, L1.z, fmaf(p2, L2.z, fmaf(p3, L3.z, acc.z))));
        acc.w = fmaf(p0, L0.w, fmaf(p1, L1.w, fmaf(p2, L2.w, fmaf(p3, L3.w, acc.w))));
    }
    for (; i < re; i++) {
        int s0 = __ldg(g_esrc + i);
        float2 ea0 = __ldg(g_eea + i);
        float4 L0 = ld_half4(g_xl2h + (long)s0 * C2, lane);
        float p0 = lrelu_dot(L0, R, ea0.x, ea0.y, W0, W1_, A);
#pragma unroll
        for (int o = 16; o > 0; o >>= 1) p0 += __shfl_xor_sync(0xffffffffu, p0, o);
        p0 = __expf(p0);
        den += p0;
        acc.x = fmaf(p0, L0.x, acc.x); acc.y = fmaf(p0, L0.y, acc.y);
        acc.z = fmaf(p0, L0.z, acc.z); acc.w = fmaf(p0, L0.w, acc.w);
    }
    float inv = 1.f / den;
    float4 bb = __ldg((const float4*)b2 + lane);
    float v0 = acc.x * inv + bb.x; v0 = v0 > 0.f ? v0 : (__expf(v0) - 1.f);
    float v1 = acc.y * inv + bb.y; v1 = v1 > 0.f ? v1 : (__expf(v1) - 1.f);
    float v2 = acc.z * inv + bb.z; v2 = v2 > 0.f ? v2 : (__expf(v2) - 1.f);
    float v3 = acc.w * inv + bb.w; v3 = v3 > 0.f ? v3 : (__expf(v3) - 1.f);
    float4 wA = __ldg((const float4*)Wfc + 2 * lane);
    float4 wB = __ldg((const float4*)Wfc + 2 * lane + 1);
    float o0 = v0 * wA.x + v1 * wA.z + v2 * wB.x + v3 * wB.z;
    float o1 = v0 * wA.y + v1 * wA.w + v2 * wB.y + v3 * wB.w;
#pragma unroll
    for (int o = 16; o > 0; o >>= 1) {
        o0 += __shfl_xor_sync(0xffffffffu, o0, o);
        o1 += __shfl_xor_sync(0xffffffffu, o1, o);
    }
    if (lane == 0) {
        out[2 * node]     = o0 + __ldg(bfc);
        out[2 * node + 1] = o1 + __ldg(bfc + 1);
    }
}

// ---------------- launch ----------------
extern "C" void kernel_launch(void* const* d_in, const int* in_sizes, int n_in,
                              void* d_out, int out_size) {
    const float* x    = (const float*)d_in[0];
    const int*   ei   = (const int*)  d_in[1];
    const float* ea   = (const float*)d_in[2];
    const int*   rt   = (const int*)  d_in[3];
    const float* aaem = (const float*)d_in[4];
    const float* W1l  = (const float*)d_in[5];
    const float* W1r  = (const float*)d_in[6];
    const float* W1e  = (const float*)d_in[7];
    const float* att1 = (const float*)d_in[8];
    const float* b1   = (const float*)d_in[9];
    const float* W2l  = (const float*)d_in[10];
    const float* W2r  = (const float*)d_in[11];
    const float* W2e  = (const float*)d_in[12];
    const float* att2 = (const float*)d_in[13];
    const float* b2   = (const float*)d_in[14];
    const float* Wfc  = (const float*)d_in[15];
    const float* bfc  = (const float*)d_in[16];
    float* out = (float*)d_out;

    int N = in_sizes[0] / 5;
    int E = in_sizes[1] / 2;
    if (N > MAXN) N = MAXN;
    if (E > MAXE) E = MAXE;
    const int* src = ei;
    const int* dst = ei + E;
    int NP_BLK = (N + 63) / 64;
    int nb = (N + 1023) / 1024;

    // lazily-created side stream + fork/join events (host resources, no device mem)
    static bool s_init = false;
    static cudaStream_t sB;
    static cudaEvent_t evF, evJ;
    if (!s_init) {
        cudaStreamCreateWithFlags(&sB, cudaStreamNonBlocking);
        cudaEventCreateWithFlags(&evF, cudaEventDisableTiming);
        cudaEventCreateWithFlags(&evJ, cudaEventDisableTiming);
        s_init = true;
    }

    // fork: preprocessing chain (edge data) on sB, concurrent with h0h+gemm1 (feature data)
    cudaEventRecord(evF, 0);
    cudaStreamWaitEvent(sB, evF, 0);
    k_init<<<(N + 255) / 256, 256, 0, sB>>>(N);
    k_deg<<<(E + 255) / 256, 256, 0, sB>>>(dst, ea, E);
    k_scan1<<<nb, 1024, 0, sB>>>(N);
    k_scatter<<<(E + 255) / 256, 256, 0, sB>>>(src, dst, ea, E, N, nb, E);
    cudaEventRecord(evJ, sB);

    k_h0h<<<(N * 6 + 255) / 256, 256>>>(x, rt, aaem, N);
    k_gemm1<<<dim3(NP_BLK, 4, 2), 256>>>(W1l, W1r, N);

    // join: edge1 needs both gemm1 outputs and CSR/loopea
    cudaStreamWaitEvent(0, evJ, 0);
    k_edge1<<<N, 128>>>(W1e, att1, b1, N);

    k_gemm2<<<dim3(NP_BLK, 1, 2), 256>>>(W2l, W2r, N);
    k_edge2<<<(N + 7) / 8, 256>>>(W2e, att2, b2, Wfc, bfc, out, N);
}